// round 1
// baseline (speedup 1.0000x reference)
#include <cuda_runtime.h>

// selfAttn2d fused kernel for B200 (sm_100a).
// One block processes PB=4 patches end-to-end; 256 threads; 192KB dynamic smem.
// All heavy contractions are register-tiled smem GEMMs in fp32.

#define PB 4
#define NT 256

__global__ __launch_bounds__(NT, 1)
void attn_kernel(const float* __restrict__ x,
                 const float* __restrict__ wq,
                 const float* __restrict__ wk,
                 const float* __restrict__ wv,
                 const float* __restrict__ w_rel,
                 const float* __restrict__ w_deconv,
                 const float* __restrict__ w_sf1,
                 const float* __restrict__ b_sf1,
                 const float* __restrict__ w_sf2,
                 const float* __restrict__ b_sf2,
                 const float* __restrict__ w_proj,
                 const float* __restrict__ b_proj,
                 float* __restrict__ out)
{
    extern __shared__ float sm[];
    float* s_q  = sm;              // [4][64][16]  q (scaled by 0.25)
    float* s_k  = sm + 4096;       // [4][64][16]
    float* s_v  = sm + 8192;       // [4][64][16]
    float* s_rc = sm + 12288;      // [4][64][16]  rel_c
    float* BIG  = sm + 16384;      // 32768 floats scratch (128KB)

    const int tid = threadIdx.x;
    const int patch0 = blockIdx.x * PB;

    // ---------------- Phase A: padded patches spp[p][c][6][6] ----------------
    float* spp = BIG;                       // 4*64*36 = 9216 floats
    for (int d = tid; d < PB * 64 * 36; d += NT) spp[d] = 0.f;
    __syncthreads();
    for (int d = tid; d < PB * 64 * 16; d += NT) {
        int j = d & 3, i = (d >> 2) & 3, c = (d >> 4) & 63, p = d >> 10;
        int patch = patch0 + p;
        int bi = patch >> 10, ho = (patch >> 5) & 31, wo = patch & 31;
        int h = ho * 2 - 1 + i, w = wo * 2 - 1 + j;
        float v = 0.f;
        if (h >= 0 && h < 64 && w >= 0 && w < 64)
            v = x[((bi * 64 + c) * 64 + h) * 64 + w];
        spp[(p * 64 + c) * 36 + (i + 1) * 6 + (j + 1)] = v;
    }
    // stage transposed wq/wk/wv: w*t[c][o]
    float* wqt = BIG + 9216;
    float* wkt = BIG + 9216 + 4096;
    float* wvt = BIG + 9216 + 8192;
    for (int d = tid; d < 4096; d += NT) {
        int o = d & 63, c = d >> 6;
        wqt[d] = wq[o * 64 + c];
        wkt[d] = wk[o * 64 + c];
        wvt[d] = wv[o * 64 + c];
    }
    __syncthreads();

    // ---------------- Phase B: q/k/v = W @ sp  (fused 3-matrix GEMM) --------
    {
        const int p  = tid >> 6;
        const int o0 = ((tid >> 2) & 15) * 4;
        const int i  = tid & 3;
        float aq[4][4] = {}, ak[4][4] = {}, av[4][4] = {};
        const float* sp_base = spp + p * 64 * 36 + (i + 1) * 6 + 1;
        #pragma unroll 4
        for (int c = 0; c < 64; c++) {
            const float* sr = sp_base + c * 36;
            float sv[4] = { sr[0], sr[1], sr[2], sr[3] };
            float4 q4 = *(const float4*)(wqt + c * 64 + o0);
            float4 k4 = *(const float4*)(wkt + c * 64 + o0);
            float4 v4 = *(const float4*)(wvt + c * 64 + o0);
            float qw[4] = { q4.x, q4.y, q4.z, q4.w };
            float kw[4] = { k4.x, k4.y, k4.z, k4.w };
            float vw[4] = { v4.x, v4.y, v4.z, v4.w };
            #pragma unroll
            for (int oo = 0; oo < 4; oo++)
                #pragma unroll
                for (int j = 0; j < 4; j++) {
                    aq[oo][j] += qw[oo] * sv[j];
                    ak[oo][j] += kw[oo] * sv[j];
                    av[oo][j] += vw[oo] * sv[j];
                }
        }
        #pragma unroll
        for (int oo = 0; oo < 4; oo++) {
            int ob = (p * 64 + o0 + oo) * 16 + i * 4;
            *(float4*)(s_q + ob) = make_float4(0.25f*aq[oo][0], 0.25f*aq[oo][1],
                                               0.25f*aq[oo][2], 0.25f*aq[oo][3]);
            *(float4*)(s_k + ob) = make_float4(ak[oo][0], ak[oo][1], ak[oo][2], ak[oo][3]);
            *(float4*)(s_v + ob) = make_float4(av[oo][0], av[oo][1], av[oo][2], av[oo][3]);
        }
    }

    // ---------------- Phase C: rel_c = conv3x3(sp, w_rel), pad 1 ------------
    float* wrs = BIG + 9216;   // reuse wqkv region: [16][9][64] = 9216 floats
    {
        const int p  = tid >> 6;
        const int o0 = ((tid >> 2) & 15) * 4;
        const int i  = tid & 3;
        float acc[4][4] = {};
        for (int cb = 0; cb < 4; cb++) {
            __syncthreads();   // prev chunk compute (and Phase B reads) done
            for (int d = tid; d < 9216; d += NT) {
                int o = d & 63, tap = (d >> 6) % 9, cc = d / 576;
                wrs[d] = w_rel[(o * 64 + cb * 16 + cc) * 9 + tap];
            }
            __syncthreads();
            #pragma unroll 2
            for (int cc = 0; cc < 16; cc++) {
                int c = cb * 16 + cc;
                const float* sr = spp + (p * 64 + c) * 36 + i * 6;
                float rows[3][6];
                #pragma unroll
                for (int di = 0; di < 3; di++)
                    #pragma unroll
                    for (int cl = 0; cl < 6; cl++)
                        rows[di][cl] = sr[di * 6 + cl];
                #pragma unroll
                for (int di = 0; di < 3; di++)
                    #pragma unroll
                    for (int dj = 0; dj < 3; dj++) {
                        float4 w4 = *(const float4*)(wrs + (cc * 9 + di * 3 + dj) * 64 + o0);
                        float ww[4] = { w4.x, w4.y, w4.z, w4.w };
                        #pragma unroll
                        for (int j = 0; j < 4; j++) {
                            float sv = rows[di][j + dj];
                            acc[0][j] += ww[0] * sv;
                            acc[1][j] += ww[1] * sv;
                            acc[2][j] += ww[2] * sv;
                            acc[3][j] += ww[3] * sv;
                        }
                    }
            }
        }
        #pragma unroll
        for (int oo = 0; oo < 4; oo++) {
            int ob = (p * 64 + o0 + oo) * 16 + i * 4;
            *(float4*)(s_rc + ob) = make_float4(acc[oo][0], acc[oo][1], acc[oo][2], acc[oo][3]);
        }
    }

    // ---------------- Phase D: rel GEMM per head + fold to rel_logits -------
    // rel_ch[p*16+ij][o'*16+pq] = sum_c rel_c[p][c][ij] * wd[c][n*16+o'][pq]
    // rel_logits[p][n][t][u]    = sum_o' q[p][n*16+o'][t] * rel_ch[p*16+t][o'*16+u]
    float* wds = BIG;            // [64][256]
    float* rch = BIG + 16384;    // [64][256]
    float rl[4][4];              // [p][n], owned coords (t = tid>>4, u = tid&15)
    {
        const int rg = tid >> 5, cg = tid & 31;
        const int pr = rg >> 1, ij0 = (rg & 1) * 8;
        const int col0 = cg * 8;
        const int tF = tid >> 4, uF = tid & 15;
        for (int n = 0; n < 4; n++) {
            __syncthreads();   // prior rch consumers / spp users done
            for (int d = tid; d < 4096; d += NT) {
                int row = d >> 6, c4 = (d & 63) * 4;
                *(float4*)(wds + row * 256 + c4) =
                    *(const float4*)(w_deconv + row * 1024 + n * 256 + c4);
            }
            __syncthreads();
            float acc[8][8] = {};
            #pragma unroll 4
            for (int c = 0; c < 64; c++) {
                const float* ap = s_rc + (pr * 64 + c) * 16 + ij0;
                float4 a0 = *(const float4*)(ap);
                float4 a1 = *(const float4*)(ap + 4);
                const float* bp = wds + c * 256 + col0;
                float4 b0 = *(const float4*)(bp);
                float4 b1 = *(const float4*)(bp + 4);
                float aa[8] = { a0.x,a0.y,a0.z,a0.w,a1.x,a1.y,a1.z,a1.w };
                float bb[8] = { b0.x,b0.y,b0.z,b0.w,b1.x,b1.y,b1.z,b1.w };
                #pragma unroll
                for (int r = 0; r < 8; r++)
                    #pragma unroll
                    for (int q2 = 0; q2 < 8; q2++)
                        acc[r][q2] += aa[r] * bb[q2];
            }
            #pragma unroll
            for (int r = 0; r < 8; r++) {
                float* dst = rch + (rg * 8 + r) * 256 + col0;
                *(float4*)(dst)     = make_float4(acc[r][0], acc[r][1], acc[r][2], acc[r][3]);
                *(float4*)(dst + 4) = make_float4(acc[r][4], acc[r][5], acc[r][6], acc[r][7]);
            }
            __syncthreads();
            #pragma unroll
            for (int p2 = 0; p2 < 4; p2++) {
                const float* qb = s_q + (p2 * 64 + n * 16) * 16 + tF;
                const float* rb = rch + (p2 * 16 + tF) * 256 + uF;
                float s = 0.f;
                #pragma unroll
                for (int op = 0; op < 16; op++)
                    s += qb[op * 16] * rb[op * 16];
                rl[p2][n] = s;
            }
        }
    }
    __syncthreads();

    // ---------------- Phase E: sf MLP hidden layer --------------------------
    float* WS1 = BIG;            // 512   w_sf1[r][f]
    float* WS2 = BIG + 512;      // 256   w_sf2[u][r]
    float* B1  = BIG + 768;      // 16
    float* B2  = BIG + 784;      // 16
    float* WP  = BIG + 1024;     // 4096  w_proj[o][f]
    float* H1  = BIG + 8192;     // 4096  [p][n][t][r]
    float* WTS = BIG + 12288;    // 4096  weights [p][n][t][u]
    float* CS  = BIG + 16384;    // 256   colsum [p][f]
    for (int d = tid; d < 512; d += NT) WS1[d] = w_sf1[d];
    for (int d = tid; d < 256; d += NT) WS2[d] = w_sf2[d];
    if (tid < 16) { B1[tid] = b_sf1[tid]; B2[tid] = b_sf2[tid]; }
    for (int d = tid; d < 4096; d += NT) WP[d] = w_proj[d];
    __syncthreads();
    #pragma unroll 1
    for (int ii = 0; ii < 16; ii++) {
        int idx = ii * 256 + tid;
        int r = idx & 15, t = (idx >> 4) & 15, n = (idx >> 8) & 3, p = idx >> 10;
        float acc = B1[r];
        const float* qb = s_q + (p * 64 + n * 16) * 16 + t;
        const float* kb = s_k + (p * 64 + n * 16) * 16 + t;
        #pragma unroll
        for (int f = 0; f < 16; f++) acc += qb[f * 16] * WS1[r * 32 + f];
        #pragma unroll
        for (int f = 0; f < 16; f++) acc += kb[f * 16] * WS1[r * 32 + 16 + f];
        H1[idx] = tanhf(acc);
    }
    __syncthreads();

    // ---------------- Phase F: logits + rel_logits, softmax over u ----------
    {
        const int t = tid >> 4, u = tid & 15;
        #pragma unroll
        for (int p = 0; p < 4; p++)
            #pragma unroll
            for (int n = 0; n < 4; n++) {
                float l = B2[u];
                const float* h = H1 + ((p * 4 + n) * 16 + t) * 16;
                #pragma unroll
                for (int r = 0; r < 16; r++) l += h[r] * WS2[u * 16 + r];
                l += rl[p][n];
                float m = l;
                m = fmaxf(m, __shfl_xor_sync(0xffffffffu, m, 8));
                m = fmaxf(m, __shfl_xor_sync(0xffffffffu, m, 4));
                m = fmaxf(m, __shfl_xor_sync(0xffffffffu, m, 2));
                m = fmaxf(m, __shfl_xor_sync(0xffffffffu, m, 1));
                float e = __expf(l - m);
                float s = e;
                s += __shfl_xor_sync(0xffffffffu, s, 8);
                s += __shfl_xor_sync(0xffffffffu, s, 4);
                s += __shfl_xor_sync(0xffffffffu, s, 2);
                s += __shfl_xor_sync(0xffffffffu, s, 1);
                WTS[((p * 4 + n) * 16 + t) * 16 + u] = e / s;
            }
    }
    __syncthreads();

    // ---------------- Phase G: attn + comb column-sum -----------------------
    // colsum[p][m*16+e] = sum_n sum_u (sum_r wts[p,n,r*4+m,u]) * v[p][n*16+e][u]
    {
        const int p = tid >> 6, m = (tid >> 4) & 3, e = tid & 15;
        float cs = 0.f;
        #pragma unroll
        for (int n = 0; n < 4; n++) {
            const float* wb = WTS + ((p * 4 + n) * 16) * 16;
            const float* vb = s_v + (p * 64 + n * 16 + e) * 16;
            #pragma unroll
            for (int u = 0; u < 16; u++) {
                float ws = wb[(m) * 16 + u] + wb[(4 + m) * 16 + u]
                         + wb[(8 + m) * 16 + u] + wb[(12 + m) * 16 + u];
                cs += ws * vb[u];
            }
        }
        CS[p * 64 + m * 16 + e] = cs;
    }
    __syncthreads();

    // ---------------- Phase H: projection + sum + output --------------------
    {
        const int p = tid & 3, o = tid >> 2;
        float acc = 16.f * b_proj[o];
        #pragma unroll
        for (int f = 0; f < 64; f++) acc += CS[p * 64 + f] * WP[o * 64 + f];
        int patch = patch0 + p;
        int bi = patch >> 10, pos = patch & 1023;
        out[(bi * 64 + o) * 1024 + pos] = acc;
    }
}

extern "C" void kernel_launch(void* const* d_in, const int* in_sizes, int n_in,
                              void* d_out, int out_size) {
    const float* x      = (const float*)d_in[0];
    const float* wq     = (const float*)d_in[1];
    const float* wk     = (const float*)d_in[2];
    const float* wv     = (const float*)d_in[3];
    const float* w_rel  = (const float*)d_in[4];
    const float* w_dec  = (const float*)d_in[5];
    const float* w_sf1  = (const float*)d_in[6];
    const float* b_sf1  = (const float*)d_in[7];
    const float* w_sf2  = (const float*)d_in[8];
    const float* b_sf2  = (const float*)d_in[9];
    const float* w_proj = (const float*)d_in[10];
    const float* b_proj = (const float*)d_in[11];
    float* out = (float*)d_out;

    const int smem = 49152 * sizeof(float);   // 192KB
    cudaFuncSetAttribute(attn_kernel, cudaFuncAttributeMaxDynamicSharedMemorySize, smem);
    attn_kernel<<<1024, NT, smem>>>(x, wq, wk, wv, w_rel, w_dec,
                                    w_sf1, b_sf1, w_sf2, b_sf2,
                                    w_proj, b_proj, out);
}

// round 3
// speedup vs baseline: 1.0634x; 1.0634x over previous
#include <cuda_runtime.h>

// selfAttn2d fused kernel, round 3: R2 design with the wds/rch overlap fixed
// (rch back at BIG+16384; 192KB dynamic smem as in R1).
#define PB 4
#define NT 512

typedef unsigned long long u64;

__device__ __forceinline__ u64 pack2(float lo, float hi) {
    u64 r;
    asm("mov.b64 %0, {%1, %2};" : "=l"(r) : "r"(__float_as_uint(lo)), "r"(__float_as_uint(hi)));
    return r;
}
__device__ __forceinline__ u64 bcast2(float x) { return pack2(x, x); }
__device__ __forceinline__ void fma2(u64& d, u64 a, u64 b) {
    asm("fma.rn.f32x2 %0, %1, %2, %0;" : "+l"(d) : "l"(a), "l"(b));
}
__device__ __forceinline__ float2 unpk2(u64 v) {
    unsigned lo, hi;
    asm("mov.b64 {%0, %1}, %2;" : "=r"(lo), "=r"(hi) : "l"(v));
    return make_float2(__uint_as_float(lo), __uint_as_float(hi));
}

__global__ __launch_bounds__(NT, 1)
void attn_kernel(const float* __restrict__ x,
                 const float* __restrict__ wq,
                 const float* __restrict__ wk,
                 const float* __restrict__ wv,
                 const float* __restrict__ w_rel,
                 const float* __restrict__ w_deconv,
                 const float* __restrict__ w_sf1,
                 const float* __restrict__ b_sf1,
                 const float* __restrict__ w_sf2,
                 const float* __restrict__ b_sf2,
                 const float* __restrict__ w_proj,
                 const float* __restrict__ b_proj,
                 float* __restrict__ out)
{
    extern __shared__ float sm[];
    float* s_q  = sm;              // [4][64][16] (scaled by 0.25)
    float* s_k  = sm + 4096;
    float* s_v  = sm + 8192;
    float* s_rc = sm + 12288;      // rel_c
    float* BIG  = sm + 16384;      // 32768 floats scratch (128KB)

    const int tid = threadIdx.x;
    const int patch0 = blockIdx.x * PB;

    // ---------------- Phase A: padded patches spp[p][c][6][6] ---------------
    float* spp = BIG;                       // 9216
    float* wqt = BIG + 9216;                // 4096  [c][o]
    float* wkt = BIG + 13312;
    float* wvt = BIG + 17408;
    for (int d = tid; d < PB * 64 * 36; d += NT) spp[d] = 0.f;
    __syncthreads();
    for (int d = tid; d < PB * 64 * 16; d += NT) {
        int j = d & 3, i = (d >> 2) & 3, c = (d >> 4) & 63, p = d >> 10;
        int patch = patch0 + p;
        int bi = patch >> 10, ho = (patch >> 5) & 31, wo = patch & 31;
        int h = ho * 2 - 1 + i, w = wo * 2 - 1 + j;
        float v = 0.f;
        if (h >= 0 && h < 64 && w >= 0 && w < 64)
            v = x[((bi * 64 + c) * 64 + h) * 64 + w];
        spp[(p * 64 + c) * 36 + (i + 1) * 6 + (j + 1)] = v;
    }
    for (int d = tid; d < 4096; d += NT) {
        int o = d & 63, c = d >> 6;
        wqt[d] = wq[o * 64 + c];
        wkt[d] = wk[o * 64 + c];
        wvt[d] = wv[o * 64 + c];
    }
    __syncthreads();

    // ---------------- Phase B: q/k/v (o-paired f32x2) -----------------------
    {
        const int p  = tid >> 7;
        const int o0 = ((tid >> 2) & 31) * 2;
        const int i  = tid & 3;
        u64 aq[4] = {0,0,0,0}, ak[4] = {0,0,0,0}, av[4] = {0,0,0,0};
        const float* sp_base = spp + p * 64 * 36 + (i + 1) * 6 + 1;
        #pragma unroll 4
        for (int c = 0; c < 64; c++) {
            const float* sr = sp_base + c * 36;
            u64 sb[4];
            #pragma unroll
            for (int j = 0; j < 4; j++) sb[j] = bcast2(sr[j]);
            u64 wqv = *(const u64*)(wqt + c * 64 + o0);
            u64 wkv = *(const u64*)(wkt + c * 64 + o0);
            u64 wvv = *(const u64*)(wvt + c * 64 + o0);
            #pragma unroll
            for (int j = 0; j < 4; j++) {
                fma2(aq[j], wqv, sb[j]);
                fma2(ak[j], wkv, sb[j]);
                fma2(av[j], wvv, sb[j]);
            }
        }
        float2 fq[4], fk[4], fv[4];
        #pragma unroll
        for (int j = 0; j < 4; j++) { fq[j] = unpk2(aq[j]); fk[j] = unpk2(ak[j]); fv[j] = unpk2(av[j]); }
        int b0 = (p * 64 + o0) * 16 + i * 4;
        *(float4*)(s_q + b0)      = make_float4(0.25f*fq[0].x, 0.25f*fq[1].x, 0.25f*fq[2].x, 0.25f*fq[3].x);
        *(float4*)(s_q + b0 + 16) = make_float4(0.25f*fq[0].y, 0.25f*fq[1].y, 0.25f*fq[2].y, 0.25f*fq[3].y);
        *(float4*)(s_k + b0)      = make_float4(fk[0].x, fk[1].x, fk[2].x, fk[3].x);
        *(float4*)(s_k + b0 + 16) = make_float4(fk[0].y, fk[1].y, fk[2].y, fk[3].y);
        *(float4*)(s_v + b0)      = make_float4(fv[0].x, fv[1].x, fv[2].x, fv[3].x);
        *(float4*)(s_v + b0 + 16) = make_float4(fv[0].y, fv[1].y, fv[2].y, fv[3].y);
    }

    // ---------------- Phase C: rel_c = conv3x3 (o-paired f32x2) -------------
    float* wrs = BIG + 9216;   // [16][9][64]
    {
        const int p  = tid >> 7;
        const int o0 = ((tid >> 2) & 31) * 2;
        const int i  = tid & 3;
        u64 acc[4] = {0,0,0,0};
        for (int cb = 0; cb < 4; cb++) {
            __syncthreads();
            for (int d = tid; d < 9216; d += NT) {
                int o = d & 63, tap = (d >> 6) % 9, cc = d / 576;
                wrs[d] = w_rel[(o * 64 + cb * 16 + cc) * 9 + tap];
            }
            __syncthreads();
            #pragma unroll 2
            for (int cc = 0; cc < 16; cc++) {
                int c = cb * 16 + cc;
                const float* sr = spp + (p * 64 + c) * 36 + i * 6;
                u64 rp[3][6];
                #pragma unroll
                for (int di = 0; di < 3; di++)
                    #pragma unroll
                    for (int cl = 0; cl < 6; cl++)
                        rp[di][cl] = bcast2(sr[di * 6 + cl]);
                #pragma unroll
                for (int di = 0; di < 3; di++)
                    #pragma unroll
                    for (int dj = 0; dj < 3; dj++) {
                        u64 wv2 = *(const u64*)(wrs + (cc * 9 + di * 3 + dj) * 64 + o0);
                        #pragma unroll
                        for (int j = 0; j < 4; j++)
                            fma2(acc[j], wv2, rp[di][j + dj]);
                    }
            }
        }
        float2 fa[4];
        #pragma unroll
        for (int j = 0; j < 4; j++) fa[j] = unpk2(acc[j]);
        int b0 = (p * 64 + o0) * 16 + i * 4;
        *(float4*)(s_rc + b0)      = make_float4(fa[0].x, fa[1].x, fa[2].x, fa[3].x);
        *(float4*)(s_rc + b0 + 16) = make_float4(fa[0].y, fa[1].y, fa[2].y, fa[3].y);
    }

    // ---------------- Phase D: rel GEMM per head + fold ---------------------
    float* wds = BIG;            // [64][256] = 16384 floats
    float* rch = BIG + 16384;    // [64][256] = 16384 floats (disjoint from wds)
    float rl[2][4];
    {
        const int rg   = tid >> 7;        // 4 row groups x 16 rows
        const int col0 = (tid & 127) * 2; // 2 cols
        const int tF = (tid >> 4) & 15, uF = tid & 15, ph = tid >> 8;
        for (int n = 0; n < 4; n++) {
            __syncthreads();
            for (int d = tid; d < 4096; d += NT) {
                int row = d >> 6, c4 = d & 63;
                ((float4*)wds)[d] = ((const float4*)(w_deconv + row * 1024 + n * 256))[c4];
            }
            __syncthreads();
            u64 aL[8] = {0,0,0,0,0,0,0,0}, aH[8] = {0,0,0,0,0,0,0,0};
            #pragma unroll 4
            for (int c = 0; c < 64; c++) {
                const u64* ap = (const u64*)(s_rc + (rg * 64 + c) * 16);
                float2 bb = *(const float2*)(wds + c * 256 + col0);
                u64 bL = bcast2(bb.x), bH = bcast2(bb.y);
                #pragma unroll
                for (int k = 0; k < 8; k++) {
                    u64 a = ap[k];
                    fma2(aL[k], a, bL);
                    fma2(aH[k], a, bH);
                }
            }
            #pragma unroll
            for (int k = 0; k < 8; k++) {
                float2 lo = unpk2(aL[k]), hi = unpk2(aH[k]);
                float* dst = rch + (rg * 16 + 2 * k) * 256 + col0;
                *(float2*)dst         = make_float2(lo.x, hi.x);
                *(float2*)(dst + 256) = make_float2(lo.y, hi.y);
            }
            __syncthreads();
            #pragma unroll
            for (int pi = 0; pi < 2; pi++) {
                int p2 = ph * 2 + pi;
                const float* qb = s_q + (p2 * 64 + n * 16) * 16 + tF;
                const float* rb = rch + (p2 * 16 + tF) * 256 + uF;
                float s = 0.f;
                #pragma unroll
                for (int op = 0; op < 16; op++)
                    s += qb[op * 16] * rb[op * 16];
                rl[pi][n] = s;
            }
        }
    }
    __syncthreads();

    // ---------------- Phase E staging (transposed weights) ------------------
    float* WS1T = BIG;            // [32f][16r]
    float* WS2T = BIG + 512;      // [16r][16u]
    float* B1   = BIG + 768;
    float* B2   = BIG + 784;
    float* WPT  = BIG + 1024;     // [64f][64o]
    float* H1   = BIG + 5120;     // [p][n][t][r]
    float* WTS  = BIG + 9216;     // [p][n][t][u]
    float* CS   = BIG + 13312;    // [p][nh][64]
    float* VT   = BIG + 13824;    // [p*16+u][65] padded transpose of v
    for (int d = tid; d < 512; d += NT) { int f = d >> 4, r = d & 15; WS1T[d] = w_sf1[r * 32 + f]; }
    if (tid < 256) { int r = tid >> 4, u = tid & 15; WS2T[tid] = w_sf2[u * 16 + r]; }
    if (tid < 16) { B1[tid] = b_sf1[tid]; B2[tid] = b_sf2[tid]; }
    for (int d = tid; d < 4096; d += NT) { int f = d >> 6, o = d & 63; WPT[d] = w_proj[o * 64 + f]; }
    for (int d = tid; d < 4096; d += NT) {
        int o = d & 63, u = (d >> 6) & 15, p = d >> 10;
        VT[(p * 16 + u) * 65 + o] = s_v[(p * 64 + o) * 16 + u];
    }
    __syncthreads();

    // ---------------- Phase E: sf MLP hidden layer --------------------------
    #pragma unroll 1
    for (int ii = 0; ii < 8; ii++) {
        int idx = ii * NT + tid;
        int r = idx & 15, t = (idx >> 4) & 15, n = (idx >> 8) & 3, p = idx >> 10;
        float acc = B1[r];
        const float* qb = s_q + (p * 64 + n * 16) * 16 + t;
        const float* kb = s_k + (p * 64 + n * 16) * 16 + t;
        #pragma unroll
        for (int f = 0; f < 16; f++) acc += qb[f * 16] * WS1T[f * 16 + r];
        #pragma unroll
        for (int f = 0; f < 16; f++) acc += kb[f * 16] * WS1T[(16 + f) * 16 + r];
        H1[idx] = tanhf(acc);
    }
    __syncthreads();

    // ---------------- Phase F: logits + softmax -----------------------------
    {
        const int ph = tid >> 8, t = (tid >> 4) & 15, u = tid & 15;
        #pragma unroll
        for (int pi = 0; pi < 2; pi++) {
            int p = ph * 2 + pi;
            #pragma unroll
            for (int n = 0; n < 4; n++) {
                float l = B2[u];
                const float* h = H1 + ((p * 4 + n) * 16 + t) * 16;
                #pragma unroll
                for (int r = 0; r < 16; r++) l += h[r] * WS2T[r * 16 + u];
                l += rl[pi][n];
                float m = l;
                m = fmaxf(m, __shfl_xor_sync(0xffffffffu, m, 8));
                m = fmaxf(m, __shfl_xor_sync(0xffffffffu, m, 4));
                m = fmaxf(m, __shfl_xor_sync(0xffffffffu, m, 2));
                m = fmaxf(m, __shfl_xor_sync(0xffffffffu, m, 1));
                float e = __expf(l - m);
                float s = e;
                s += __shfl_xor_sync(0xffffffffu, s, 8);
                s += __shfl_xor_sync(0xffffffffu, s, 4);
                s += __shfl_xor_sync(0xffffffffu, s, 2);
                s += __shfl_xor_sync(0xffffffffu, s, 1);
                WTS[((p * 4 + n) * 16 + t) * 16 + u] = e / s;
            }
        }
    }
    __syncthreads();

    // ---------------- Phase G: attn + comb column-sum -----------------------
    {
        const int p = tid >> 7, z = tid & 127;
        const int nh = z >> 6, m = (z >> 4) & 3, e = z & 15;
        float cs = 0.f;
        #pragma unroll
        for (int nn = 0; nn < 2; nn++) {
            int n = nh * 2 + nn;
            const float* wb = WTS + ((p * 4 + n) * 16) * 16;
            #pragma unroll
            for (int u = 0; u < 16; u++) {
                float ws = wb[m * 16 + u] + wb[(4 + m) * 16 + u]
                         + wb[(8 + m) * 16 + u] + wb[(12 + m) * 16 + u];
                cs += ws * VT[(p * 16 + u) * 65 + n * 16 + e];
            }
        }
        CS[(p * 2 + nh) * 64 + m * 16 + e] = cs;
    }
    __syncthreads();

    // ---------------- Phase H: projection + sum + output --------------------
    if (tid < 256) {
        const int p = tid & 3, o = tid >> 2;
        float acc = 16.f * b_proj[o];
        #pragma unroll
        for (int f = 0; f < 64; f++)
            acc += (CS[(p * 2) * 64 + f] + CS[(p * 2 + 1) * 64 + f]) * WPT[f * 64 + o];
        int patch = patch0 + p;
        int bi = patch >> 10, pos = patch & 1023;
        out[(bi * 64 + o) * 1024 + pos] = acc;
    }
}

extern "C" void kernel_launch(void* const* d_in, const int* in_sizes, int n_in,
                              void* d_out, int out_size) {
    const float* x      = (const float*)d_in[0];
    const float* wq     = (const float*)d_in[1];
    const float* wk     = (const float*)d_in[2];
    const float* wv     = (const float*)d_in[3];
    const float* w_rel  = (const float*)d_in[4];
    const float* w_dec  = (const float*)d_in[5];
    const float* w_sf1  = (const float*)d_in[6];
    const float* b_sf1  = (const float*)d_in[7];
    const float* w_sf2  = (const float*)d_in[8];
    const float* b_sf2  = (const float*)d_in[9];
    const float* w_proj = (const float*)d_in[10];
    const float* b_proj = (const float*)d_in[11];
    float* out = (float*)d_out;

    const int smem = 49152 * sizeof(float);   // 192KB
    cudaFuncSetAttribute(attn_kernel, cudaFuncAttributeMaxDynamicSharedMemorySize, smem);
    attn_kernel<<<1024, NT, smem>>>(x, wq, wk, wv, w_rel, w_dec,
                                    w_sf1, b_sf1, w_sf2, b_sf2,
                                    w_proj, b_proj, out);
}